// round 2
// baseline (speedup 1.0000x reference)
#include <cuda_runtime.h>
#include <math_constants.h>

// Problem constants
#define NLAG   12          // LAG-1
#define NB     32          // batch
#define NN     1200        // N
#define MROWS  1152        // 3 * NLAG * NB
#define KDIM   1200

// Scratch (no allocations allowed)
__device__ float g_X[MROWS * KDIM];   // packed GEMM A operand
__device__ float g_C[MROWS * NN];     // tanh(-X @ WW)
__device__ float g_belta[NLAG];
__device__ float g_c2[NLAG];
__device__ float g_pf[NLAG];

__device__ __forceinline__ float gamma_fn(float x) {
    if (x > 0.f) return expf(lgammaf(x));
    return CUDART_PI_F / (sinf(CUDART_PI_F * x) * expf(lgammaf(1.f - x)));
}

// ---------------------------------------------------------------------------
// Per-lag scalars (12): belta, c2 = G(a+1)/(6 G(a-2)), pf = 2*3^fract
// ---------------------------------------------------------------------------
__global__ void scalars_kernel(const float* __restrict__ alpha,
                               const float* __restrict__ fract) {
    int lag = threadIdx.x;
    if (lag >= NLAG) return;
    float a   = alpha[lag];
    float f   = fract[lag];
    float ga1 = gamma_fn(a + 1.f);
    float gm2 = gamma_fn(a - 2.f);
    float belta = 1.f                              // kk=0
                + ga1 / gamma_fn(a)                // kk=1
                + ga1 / (2.f * gamma_fn(a - 1.f))  // kk=2
                + ga1 / (6.f * gm2);               // kk=3
    g_belta[lag] = belta;
    g_c2[lag]    = ga1 / (6.f * gm2);
    g_pf[lag]    = 2.f * powf(3.f, f);
}

// ---------------------------------------------------------------------------
// Pack three GEMM-A operands into one 1152 x 1200 matrix:
// rows [0,384):    A[lag,b,i]
// rows [384,768):  train_init[b,i,lag+1,1]   (A_0_NEW)
// rows [768,1152): train_init[b,i,lag,  1]   (A_N_OLD)
// ---------------------------------------------------------------------------
__global__ void pack_kernel(const float* __restrict__ A,
                            const float* __restrict__ train_init) {
    int idx = blockIdx.x * blockDim.x + threadIdx.x;
    if (idx >= MROWS * KDIM) return;
    int r = idx / KDIM;
    int i = idx - r * KDIM;
    float v;
    if (r < 384) {
        v = A[idx];
    } else {
        int rr  = r - 384;
        int mat = rr / 384;
        rr      = rr % 384;
        int lag = rr / NB;
        int b   = rr % NB;
        int lagidx = (mat == 0) ? (lag + 1) : lag;
        v = train_init[((b * NN + i) * 13 + lagidx) * 2 + 1];
    }
    g_X[idx] = v;
}

// ---------------------------------------------------------------------------
// FFMA2 (packed f32x2) tiled GEMM: C = tanh(-(X @ WW))
// BM=64, BN=128, BK=16, 256 threads, 4 rows x 4 col-pairs per thread.
// ---------------------------------------------------------------------------
#define BM 64
#define BN 128
#define BK 16
#define BMP 68   // padded As row (keeps 16B alignment, avoids store conflicts)

typedef unsigned long long u64;

__device__ __forceinline__ void ffma2(u64& d, u64 a, u64 b) {
    asm("fma.rn.f32x2 %0, %1, %2, %0;" : "+l"(d) : "l"(a), "l"(b));
}
__device__ __forceinline__ u64 pack2(float lo, float hi) {
    u64 r;
    asm("mov.b64 %0, {%1, %2};" : "=l"(r) : "f"(lo), "f"(hi));
    return r;
}
__device__ __forceinline__ void unpack2(float& lo, float& hi, u64 v) {
    asm("mov.b64 {%0, %1}, %2;" : "=f"(lo), "=f"(hi) : "l"(v));
}

__global__ __launch_bounds__(256, 2)
void gemm_tanh_kernel(const float* __restrict__ Bmat) {
    __shared__ float As[BK][BMP];      // k-major
    __shared__ float Bs[BK][BN];

    const int tid = threadIdx.x;
    const int m0  = blockIdx.y * BM;
    const int n0  = blockIdx.x * BN;
    const int ty  = tid >> 4;          // 0..15 : m-group (4 rows)
    const int tx  = tid & 15;          // 0..15 : n-group (8 cols = 4 pairs)

    // A loader: 64 rows x 16 k, one float4 per thread
    const int arow  = tid >> 2;            // 0..63
    const int akcol = (tid & 3) << 2;      // 0,4,8,12
    // B loader: 16 k x 128 n, two float4 per thread
    const int brow  = tid >> 4;            // 0..15
    const int bcol  = (tid & 15) << 3;     // 0..120 step 8

    u64 acc[4][4];
#pragma unroll
    for (int i = 0; i < 4; i++)
#pragma unroll
        for (int j = 0; j < 4; j++) acc[i][j] = 0ULL;

    const bool bv0 = (n0 + bcol)     < NN;
    const bool bv1 = (n0 + bcol + 4) < NN;

    for (int k0 = 0; k0 < KDIM; k0 += BK) {
        float4 av = *reinterpret_cast<const float4*>(
            &g_X[(m0 + arow) * KDIM + k0 + akcol]);
        As[akcol + 0][arow] = av.x;
        As[akcol + 1][arow] = av.y;
        As[akcol + 2][arow] = av.z;
        As[akcol + 3][arow] = av.w;

        float4 b0 = make_float4(0.f, 0.f, 0.f, 0.f);
        float4 b1 = make_float4(0.f, 0.f, 0.f, 0.f);
        const float* brp = &Bmat[(k0 + brow) * NN + n0 + bcol];
        if (bv0) b0 = *reinterpret_cast<const float4*>(brp);
        if (bv1) b1 = *reinterpret_cast<const float4*>(brp + 4);
        *reinterpret_cast<float4*>(&Bs[brow][bcol])     = b0;
        *reinterpret_cast<float4*>(&Bs[brow][bcol + 4]) = b1;

        __syncthreads();

#pragma unroll
        for (int k = 0; k < BK; k++) {
            float4 ra = *reinterpret_cast<const float4*>(&As[k][ty << 2]);
            const u64* bp = reinterpret_cast<const u64*>(&Bs[k][tx << 3]);
            u64 rb0 = bp[0], rb1 = bp[1], rb2 = bp[2], rb3 = bp[3];
            u64 pa0 = pack2(ra.x, ra.x);
            u64 pa1 = pack2(ra.y, ra.y);
            u64 pa2 = pack2(ra.z, ra.z);
            u64 pa3 = pack2(ra.w, ra.w);
            ffma2(acc[0][0], pa0, rb0); ffma2(acc[0][1], pa0, rb1);
            ffma2(acc[0][2], pa0, rb2); ffma2(acc[0][3], pa0, rb3);
            ffma2(acc[1][0], pa1, rb0); ffma2(acc[1][1], pa1, rb1);
            ffma2(acc[1][2], pa1, rb2); ffma2(acc[1][3], pa1, rb3);
            ffma2(acc[2][0], pa2, rb0); ffma2(acc[2][1], pa2, rb1);
            ffma2(acc[2][2], pa2, rb2); ffma2(acc[2][3], pa2, rb3);
            ffma2(acc[3][0], pa3, rb0); ffma2(acc[3][1], pa3, rb1);
            ffma2(acc[3][2], pa3, rb2); ffma2(acc[3][3], pa3, rb3);
        }
        __syncthreads();
    }

#pragma unroll
    for (int i = 0; i < 4; i++) {
        int row = m0 + (ty << 2) + i;
#pragma unroll
        for (int j = 0; j < 4; j++) {
            int col = n0 + (tx << 3) + j * 2;
            float lo, hi;
            unpack2(lo, hi, acc[i][j]);
            if (col < NN)     g_C[row * NN + col]     = tanhf(-lo);
            if (col + 1 < NN) g_C[row * NN + col + 1] = tanhf(-hi);
        }
    }
}

// ---------------------------------------------------------------------------
// Epilogue: out[b,lag,j] = lambd/belta * ( pf*OUT + 3*l*(A0NEW + c2*ANOLD) )
// ---------------------------------------------------------------------------
__global__ void epilogue_kernel(const float* __restrict__ lambd,
                                const float* __restrict__ l,
                                float* __restrict__ out) {
    int idx = blockIdx.x * blockDim.x + threadIdx.x;
    const int total = NB * NLAG * NN;
    if (idx >= total) return;
    int j   = idx % NN;
    int lag = (idx / NN) % NLAG;
    int b   = idx / (NN * NLAG);
    int jm  = j % 200;

    int r = lag * NB + b;
    float outv = g_C[r * NN + j];
    float a0   = g_C[(384 + r) * NN + j];
    float an   = g_C[(768 + r) * NN + j];

    float lam = lambd[lag * 200 + jm];
    float lv  = l[lag * 200 + jm];

    out[idx] = lam / g_belta[lag] *
               (g_pf[lag] * outv + 3.f * lv * (a0 + g_c2[lag] * an));
}

// ---------------------------------------------------------------------------
extern "C" void kernel_launch(void* const* d_in, const int* in_sizes, int n_in,
                              void* d_out, int out_size) {
    const float* A          = (const float*)d_in[0];
    const float* WW         = (const float*)d_in[1];
    const float* train_init = (const float*)d_in[2];
    const float* alpha      = (const float*)d_in[3];
    const float* fract      = (const float*)d_in[4];
    const float* lambd      = (const float*)d_in[5];
    const float* l          = (const float*)d_in[6];
    float* out = (float*)d_out;

    scalars_kernel<<<1, 32>>>(alpha, fract);

    const int packN = MROWS * KDIM;
    pack_kernel<<<(packN + 255) / 256, 256>>>(A, train_init);

    dim3 grid((NN + BN - 1) / BN, MROWS / BM);  // (10, 18)
    gemm_tanh_kernel<<<grid, 256>>>(WW);

    const int total = NB * NLAG * NN;
    epilogue_kernel<<<(total + 255) / 256, 256>>>(lambd, l, out);
}

// round 4
// speedup vs baseline: 3.6786x; 3.6786x over previous
#include <cuda_runtime.h>
#include <cuda_bf16.h>
#include <math_constants.h>
#include <cstdint>

// Problem constants
#define NLAG   12
#define NB     32
#define NN     1200
#define MROWS  1152          // 3 * NLAG * NB
#define KDIM   1200
#define KP     1216          // K padded to 38*32
#define NP     1280          // N padded to 10*128

// GEMM tiling
#define BK       32
#define NCHUNK   (KP / BK)   // 38
#define ROWB     80          // padded smem row bytes (32 bf16 = 64B + 16B pad)
#define TILEB    (128 * ROWB)
#define STAGEB   (4 * TILEB) // A0,A1,B0,B1 per stage

// Scratch (device globals; no allocation allowed)
__device__ __align__(16) __nv_bfloat16 g_A0[MROWS * KP];
__device__ __align__(16) __nv_bfloat16 g_A1[MROWS * KP];
__device__ __align__(16) __nv_bfloat16 g_B0[NP * KP];
__device__ __align__(16) __nv_bfloat16 g_B1[NP * KP];
__device__ __align__(16) float g_C[MROWS * NN];
__device__ float g_belta[NLAG];
__device__ float g_c2[NLAG];
__device__ float g_pf[NLAG];

// ---------------------------------------------------------------------------
__device__ __forceinline__ uint32_t smem_u32(const void* p) {
    uint32_t a;
    asm("{ .reg .u64 t; cvta.to.shared.u64 t, %1; cvt.u32.u64 %0, t; }"
        : "=r"(a) : "l"(p));
    return a;
}

#define LDSM4(r, addr)                                                      \
    asm volatile("ldmatrix.sync.aligned.m8n8.x4.shared.b16 "                \
                 "{%0, %1, %2, %3}, [%4];"                                  \
                 : "=r"((r)[0]), "=r"((r)[1]), "=r"((r)[2]), "=r"((r)[3])   \
                 : "r"(addr))

#define MMA_BF16(c, a, bb0, bb1)                                            \
    asm volatile("mma.sync.aligned.m16n8k16.row.col.f32.bf16.bf16.f32 "     \
                 "{%0, %1, %2, %3}, {%4, %5, %6, %7}, {%8, %9}, "           \
                 "{%0, %1, %2, %3};"                                        \
                 : "+f"((c)[0]), "+f"((c)[1]), "+f"((c)[2]), "+f"((c)[3])   \
                 : "r"((a)[0]), "r"((a)[1]), "r"((a)[2]), "r"((a)[3]),      \
                   "r"(bb0), "r"(bb1))

// ---------------------------------------------------------------------------
__device__ __forceinline__ float gamma_fn(float x) {
    if (x > 0.f) return expf(lgammaf(x));
    return CUDART_PI_F / (sinf(CUDART_PI_F * x) * expf(lgammaf(1.f - x)));
}

__global__ void scalars_kernel(const float* __restrict__ alpha,
                               const float* __restrict__ fract) {
    int lag = threadIdx.x;
    if (lag >= NLAG) return;
    float a   = alpha[lag];
    float f   = fract[lag];
    float ga1 = gamma_fn(a + 1.f);
    float gm2 = gamma_fn(a - 2.f);
    float belta = 1.f
                + ga1 / gamma_fn(a)
                + ga1 / (2.f * gamma_fn(a - 1.f))
                + ga1 / (6.f * gm2);
    g_belta[lag] = belta;
    g_c2[lag]    = ga1 / (6.f * gm2);
    g_pf[lag]    = 2.f * powf(3.f, f);
}

// ---------------------------------------------------------------------------
// Pack A operand (3 stacked matrices) into split bf16 (hi + residual), padded.
// rows [0,384):    A[lag,b,i]
// rows [384,768):  train_init[b,i,lag+1,1]
// rows [768,1152): train_init[b,i,lag,  1]
// ---------------------------------------------------------------------------
__global__ void pack_A_kernel(const float* __restrict__ A,
                              const float* __restrict__ train_init) {
    int idx = blockIdx.x * blockDim.x + threadIdx.x;
    if (idx >= MROWS * KP) return;
    int r = idx / KP;
    int k = idx - r * KP;
    float v = 0.f;
    if (k < KDIM) {
        if (r < 384) {
            v = A[r * KDIM + k];
        } else {
            int rr  = r - 384;
            int mat = rr / 384;
            rr      = rr % 384;
            int lag = rr / NB;
            int b   = rr % NB;
            int lagidx = (mat == 0) ? (lag + 1) : lag;
            v = train_init[((b * NN + k) * 13 + lagidx) * 2 + 1];
        }
    }
    __nv_bfloat16 hi = __float2bfloat16(v);
    __nv_bfloat16 lo = __float2bfloat16(v - __bfloat162float(hi));
    g_A0[idx] = hi;
    g_A1[idx] = lo;
}

// ---------------------------------------------------------------------------
// Pack B: transposed WW -> g_B[n][k] = WW[k][n], split bf16, zero-padded.
// Grid covers the full padded [NP, KP] array.
// ---------------------------------------------------------------------------
__global__ void pack_B_kernel(const float* __restrict__ WW) {
    __shared__ float tile[32][33];
    int k0 = blockIdx.x * 32;
    int n0 = blockIdx.y * 32;
    int tx = threadIdx.x, ty = threadIdx.y;   // 32 x 8
#pragma unroll
    for (int i = 0; i < 4; i++) {
        int k = k0 + ty + i * 8;
        int n = n0 + tx;
        tile[ty + i * 8][tx] = (k < KDIM && n < NN) ? WW[k * NN + n] : 0.f;
    }
    __syncthreads();
#pragma unroll
    for (int i = 0; i < 4; i++) {
        int n = n0 + ty + i * 8;
        int k = k0 + tx;
        if (n < NP && k < KP) {
            float v = tile[tx][ty + i * 8];
            __nv_bfloat16 hi = __float2bfloat16(v);
            __nv_bfloat16 lo = __float2bfloat16(v - __bfloat162float(hi));
            g_B0[n * KP + k] = hi;
            g_B1[n * KP + k] = lo;
        }
    }
}

// ---------------------------------------------------------------------------
// Split-bf16 HMMA GEMM: g_C = tanh(-(X @ WW)).
// CTA 128x128, 8 warps (64m x 32n each), BK=32 double-buffered.
// ---------------------------------------------------------------------------
__global__ __launch_bounds__(256, 1)
void gemm_mma_kernel() {
    extern __shared__ __align__(16) char smem[];
    const uint32_t sb = smem_u32(smem);
    const int tid  = threadIdx.x;
    const int lane = tid & 31;
    const int wid  = tid >> 5;
    const int wm   = wid >> 2;       // 0..1
    const int wn   = wid & 3;        // 0..3
    const int m0   = blockIdx.y * 128;
    const int n0   = blockIdx.x * 128;

    const __nv_bfloat16* srcs[4] = {
        g_A0 + (size_t)m0 * KP, g_A1 + (size_t)m0 * KP,
        g_B0 + (size_t)n0 * KP, g_B1 + (size_t)n0 * KP
    };

    // global<->smem copy mapping: idx = tid + 256*i -> row = idx>>2, seg = idx&3
    const int row0 = tid >> 2;       // rows 0..63 (i=0), +64 (i=1)
    const int seg  = tid & 3;        // 16B segment within 64B row payload

    // ldmatrix lane addressing
    const int jm = lane >> 3, rr = lane & 7;
    const uint32_t a_l = (uint32_t)((wm * 64 + (jm & 1) * 8 + rr) * ROWB + (jm >> 1) * 16);
    const uint32_t b_l = (uint32_t)((wn * 32 + (jm >> 1) * 8 + rr) * ROWB + (jm & 1) * 16);

    float acc[4][4][4];
#pragma unroll
    for (int mf = 0; mf < 4; mf++)
#pragma unroll
        for (int n = 0; n < 4; n++)
#pragma unroll
            for (int e = 0; e < 4; e++) acc[mf][n][e] = 0.f;

    // Prologue: load chunk 0 into stage 0
    uint4 v[4][2];
#pragma unroll
    for (int t = 0; t < 4; t++)
#pragma unroll
        for (int i = 0; i < 2; i++)
            v[t][i] = *reinterpret_cast<const uint4*>(
                srcs[t] + (size_t)(row0 + i * 64) * KP + seg * 8);
#pragma unroll
    for (int t = 0; t < 4; t++)
#pragma unroll
        for (int i = 0; i < 2; i++)
            *reinterpret_cast<uint4*>(
                smem + t * TILEB + (row0 + i * 64) * ROWB + seg * 16) = v[t][i];
    __syncthreads();

    for (int c = 0; c < NCHUNK; c++) {
        const int cur = c & 1;
        const bool pf = (c + 1 < NCHUNK);
        if (pf) {
            const int k0 = (c + 1) * BK;
#pragma unroll
            for (int t = 0; t < 4; t++)
#pragma unroll
                for (int i = 0; i < 2; i++)
                    v[t][i] = *reinterpret_cast<const uint4*>(
                        srcs[t] + (size_t)(row0 + i * 64) * KP + k0 + seg * 8);
        }

        const uint32_t base = sb + cur * STAGEB;
#pragma unroll
        for (int ks = 0; ks < 2; ks++) {
            const uint32_t koff = ks * 32;
            uint32_t A0f[4][4], A1f[4][4];
#pragma unroll
            for (int mf = 0; mf < 4; mf++) {
                LDSM4(A0f[mf], base + 0 * TILEB + a_l + mf * (16 * ROWB) + koff);
                LDSM4(A1f[mf], base + 1 * TILEB + a_l + mf * (16 * ROWB) + koff);
            }
            uint32_t B0f[2][4], B1f[2][4];
#pragma unroll
            for (int np = 0; np < 2; np++) {
                LDSM4(B0f[np], base + 2 * TILEB + b_l + np * (16 * ROWB) + koff);
                LDSM4(B1f[np], base + 3 * TILEB + b_l + np * (16 * ROWB) + koff);
            }
#pragma unroll
            for (int mf = 0; mf < 4; mf++)
#pragma unroll
                for (int n = 0; n < 4; n++) {
                    const int np = n >> 1, s = (n & 1) * 2;
                    MMA_BF16(acc[mf][n], A0f[mf], B0f[np][s], B0f[np][s + 1]);
                    MMA_BF16(acc[mf][n], A0f[mf], B1f[np][s], B1f[np][s + 1]);
                    MMA_BF16(acc[mf][n], A1f[mf], B0f[np][s], B0f[np][s + 1]);
                }
        }

        if (pf) {
            char* dst = smem + (cur ^ 1) * STAGEB;
#pragma unroll
            for (int t = 0; t < 4; t++)
#pragma unroll
                for (int i = 0; i < 2; i++)
                    *reinterpret_cast<uint4*>(
                        dst + t * TILEB + (row0 + i * 64) * ROWB + seg * 16) = v[t][i];
        }
        __syncthreads();
    }

    // Epilogue: tanh(-x) and store
    const int gid = lane >> 2, tig = lane & 3;
#pragma unroll
    for (int mf = 0; mf < 4; mf++) {
        const int row = m0 + wm * 64 + mf * 16 + gid;
#pragma unroll
        for (int n = 0; n < 4; n++) {
            const int col = n0 + wn * 32 + n * 8 + tig * 2;
            if (col < NN) {
                float2 lo, hi;
                lo.x = tanhf(-acc[mf][n][0]);
                lo.y = tanhf(-acc[mf][n][1]);
                hi.x = tanhf(-acc[mf][n][2]);
                hi.y = tanhf(-acc[mf][n][3]);
                *reinterpret_cast<float2*>(&g_C[(size_t)row * NN + col])       = lo;
                *reinterpret_cast<float2*>(&g_C[(size_t)(row + 8) * NN + col]) = hi;
            }
        }
    }
}

// ---------------------------------------------------------------------------
// Final combine: out[b,lag,j] = lambd/belta * ( pf*OUT + 3*l*(A0NEW + c2*ANOLD) )
// ---------------------------------------------------------------------------
__global__ void epilogue_kernel(const float* __restrict__ lambd,
                                const float* __restrict__ l,
                                float* __restrict__ out) {
    int idx = blockIdx.x * blockDim.x + threadIdx.x;
    const int total = NB * NLAG * NN;
    if (idx >= total) return;
    int j   = idx % NN;
    int lag = (idx / NN) % NLAG;
    int b   = idx / (NN * NLAG);
    int jm  = j % 200;

    int r = lag * NB + b;
    float outv = g_C[r * NN + j];
    float a0   = g_C[(384 + r) * NN + j];
    float an   = g_C[(768 + r) * NN + j];

    float lam = lambd[lag * 200 + jm];
    float lv  = l[lag * 200 + jm];

    out[idx] = lam / g_belta[lag] *
               (g_pf[lag] * outv + 3.f * lv * (a0 + g_c2[lag] * an));
}

// ---------------------------------------------------------------------------
extern "C" void kernel_launch(void* const* d_in, const int* in_sizes, int n_in,
                              void* d_out, int out_size) {
    const float* A          = (const float*)d_in[0];
    const float* WW         = (const float*)d_in[1];
    const float* train_init = (const float*)d_in[2];
    const float* alpha      = (const float*)d_in[3];
    const float* fract      = (const float*)d_in[4];
    const float* lambd      = (const float*)d_in[5];
    const float* l          = (const float*)d_in[6];
    float* out = (float*)d_out;

    cudaFuncSetAttribute(gemm_mma_kernel,
                         cudaFuncAttributeMaxDynamicSharedMemorySize,
                         2 * STAGEB);

    scalars_kernel<<<1, 32>>>(alpha, fract);

    pack_A_kernel<<<(MROWS * KP + 255) / 256, 256>>>(A, train_init);

    dim3 tgrid(KP / 32, NP / 32);                 // (38, 40)
    pack_B_kernel<<<tgrid, dim3(32, 8)>>>(WW);

    dim3 ggrid(NP / 128, MROWS / 128);            // (10, 9)
    gemm_mma_kernel<<<ggrid, 256, 2 * STAGEB>>>();

    const int total = NB * NLAG * NN;
    epilogue_kernel<<<(total + 255) / 256, 256>>>(lambd, l, out);
}

// round 5
// speedup vs baseline: 3.9630x; 1.0773x over previous
#include <cuda_runtime.h>
#include <cuda_bf16.h>
#include <math_constants.h>
#include <cstdint>

// Problem constants
#define NLAG   12
#define NB     32
#define NN     1200
#define MROWS  1152          // 3 * NLAG * NB
#define KDIM   1200
#define KP     1216          // K padded to 38*32
#define NP     1280          // N padded to 8*160

// GEMM tiling: CTA tile 64m x 160n, BK=32, 512 threads (16 warps, 16m x 40n each)
#define BK      32
#define NCHUNK  (KP / BK)    // 38
#define AROWB   80           // A smem row pitch (32 bf16 = 64B + 16B pad)
#define BROWB   336          // B smem row pitch (160 bf16 = 320B + 16B pad)
#define A_TILE  (64 * AROWB)     // 5120
#define B_TILE  (32 * BROWB)     // 10752
#define OFF_A0  0
#define OFF_A1  A_TILE
#define OFF_B0  (2 * A_TILE)
#define OFF_B1  (2 * A_TILE + B_TILE)
#define STAGE   (2 * A_TILE + 2 * B_TILE)   // 31744
#define NUNITS  1792         // 16B units per chunk: B 2*640 + A 2*256

// Scratch (device globals; no allocation allowed)
__device__ __align__(16) __nv_bfloat16 g_A0[MROWS * KP];
__device__ __align__(16) __nv_bfloat16 g_A1[MROWS * KP];
__device__ __align__(16) __nv_bfloat16 g_B0[KP * NP];    // k-major!
__device__ __align__(16) __nv_bfloat16 g_B1[KP * NP];
__device__ __align__(16) float g_C[MROWS * NN];
__device__ float g_belta[NLAG];
__device__ float g_c2[NLAG];
__device__ float g_pf[NLAG];

// ---------------------------------------------------------------------------
__device__ __forceinline__ uint32_t smem_u32(const void* p) {
    uint32_t a;
    asm("{ .reg .u64 t; cvta.to.shared.u64 t, %1; cvt.u32.u64 %0, t; }"
        : "=r"(a) : "l"(p));
    return a;
}

#define LDSM4(r, addr)                                                      \
    asm volatile("ldmatrix.sync.aligned.m8n8.x4.shared.b16 "                \
                 "{%0, %1, %2, %3}, [%4];"                                  \
                 : "=r"((r)[0]), "=r"((r)[1]), "=r"((r)[2]), "=r"((r)[3])   \
                 : "r"(addr))
#define LDSM4T(r, addr)                                                     \
    asm volatile("ldmatrix.sync.aligned.m8n8.x4.trans.shared.b16 "          \
                 "{%0, %1, %2, %3}, [%4];"                                  \
                 : "=r"((r)[0]), "=r"((r)[1]), "=r"((r)[2]), "=r"((r)[3])   \
                 : "r"(addr))
#define LDSM2T(r, addr)                                                     \
    asm volatile("ldmatrix.sync.aligned.m8n8.x2.trans.shared.b16 "          \
                 "{%0, %1}, [%2];"                                          \
                 : "=r"((r)[0]), "=r"((r)[1]) : "r"(addr))

#define MMA_BF16(c, a, bb0, bb1)                                            \
    asm volatile("mma.sync.aligned.m16n8k16.row.col.f32.bf16.bf16.f32 "     \
                 "{%0, %1, %2, %3}, {%4, %5, %6, %7}, {%8, %9}, "           \
                 "{%0, %1, %2, %3};"                                        \
                 : "+f"((c)[0]), "+f"((c)[1]), "+f"((c)[2]), "+f"((c)[3])   \
                 : "r"((a)[0]), "r"((a)[1]), "r"((a)[2]), "r"((a)[3]),      \
                   "r"(bb0), "r"(bb1))

#define CP_ASYNC16(dst, src)                                                \
    asm volatile("cp.async.cg.shared.global [%0], [%1], 16;"                \
                 :: "r"(dst), "l"(__cvta_generic_to_global(src)))
#define CP_COMMIT() asm volatile("cp.async.commit_group;" ::: "memory")
#define CP_WAIT1()  asm volatile("cp.async.wait_group 1;" ::: "memory")
#define CP_WAIT0()  asm volatile("cp.async.wait_group 0;" ::: "memory")

// ---------------------------------------------------------------------------
__device__ __forceinline__ float gamma_fn(float x) {
    if (x > 0.f) return expf(lgammaf(x));
    return CUDART_PI_F / (sinf(CUDART_PI_F * x) * expf(lgammaf(1.f - x)));
}

__global__ void scalars_kernel(const float* __restrict__ alpha,
                               const float* __restrict__ fract) {
    int lag = threadIdx.x;
    if (lag >= NLAG) return;
    float a   = alpha[lag];
    float f   = fract[lag];
    float ga1 = gamma_fn(a + 1.f);
    float gm2 = gamma_fn(a - 2.f);
    float belta = 1.f
                + ga1 / gamma_fn(a)
                + ga1 / (2.f * gamma_fn(a - 1.f))
                + ga1 / (6.f * gm2);
    g_belta[lag] = belta;
    g_c2[lag]    = ga1 / (6.f * gm2);
    g_pf[lag]    = 2.f * powf(3.f, f);
}

// ---------------------------------------------------------------------------
// Pack A operand (3 stacked matrices) into split bf16 (hi + residual), padded.
// ---------------------------------------------------------------------------
__global__ void pack_A_kernel(const float* __restrict__ A,
                              const float* __restrict__ train_init) {
    int idx = blockIdx.x * blockDim.x + threadIdx.x;
    if (idx >= MROWS * KP) return;
    int r = idx / KP;
    int k = idx - r * KP;
    float v = 0.f;
    if (k < KDIM) {
        if (r < 384) {
            v = A[r * KDIM + k];
        } else {
            int rr  = r - 384;
            int mat = rr / 384;
            rr      = rr % 384;
            int lag = rr / NB;
            int b   = rr % NB;
            int lagidx = (mat == 0) ? (lag + 1) : lag;
            v = train_init[((b * NN + k) * 13 + lagidx) * 2 + 1];
        }
    }
    __nv_bfloat16 hi = __float2bfloat16(v);
    __nv_bfloat16 lo = __float2bfloat16(v - __bfloat162float(hi));
    g_A0[idx] = hi;
    g_A1[idx] = lo;
}

// ---------------------------------------------------------------------------
// Pack B: k-major split (NO transpose; ldmatrix.trans handles layout).
// g_B[k][n] = WW[k][n], zero-padded to [KP, NP].
// ---------------------------------------------------------------------------
__global__ void pack_B_kernel(const float* __restrict__ WW) {
    int idx = blockIdx.x * blockDim.x + threadIdx.x;   // over KP * NP/2
    if (idx >= KP * (NP / 2)) return;
    int k = idx / (NP / 2);
    int n = (idx - k * (NP / 2)) * 2;
    float v0 = 0.f, v1 = 0.f;
    if (k < KDIM && n + 1 < NN) {
        float2 w = *reinterpret_cast<const float2*>(&WW[k * NN + n]);
        v0 = w.x; v1 = w.y;
    } else if (k < KDIM && n < NN) {
        v0 = WW[k * NN + n];
    }
    __nv_bfloat16 h0 = __float2bfloat16(v0);
    __nv_bfloat16 l0 = __float2bfloat16(v0 - __bfloat162float(h0));
    __nv_bfloat16 h1 = __float2bfloat16(v1);
    __nv_bfloat16 l1 = __float2bfloat16(v1 - __bfloat162float(h1));
    reinterpret_cast<__nv_bfloat162*>(g_B0)[idx] = __halves2bfloat162(h0, h1);
    reinterpret_cast<__nv_bfloat162*>(g_B1)[idx] = __halves2bfloat162(l0, l1);
}

// ---------------------------------------------------------------------------
// cp.async issue for one chunk: 1792 16B units (B0,B1: 32x320B; A0,A1: 64x64B)
// ---------------------------------------------------------------------------
__device__ __forceinline__ void issue_chunk(uint32_t stage, int m0, int n0,
                                            int k0, int tid) {
#pragma unroll
    for (int i = 0; i < 4; i++) {
        int u = tid + i * 512;
        if (u < NUNITS) {
            uint32_t dst;
            const __nv_bfloat16* src;
            if (u < 1280) {                 // B tiles: 2 x 640 units
                int t   = u >= 640;
                int v   = u - t * 640;
                int row = v / 20;
                int seg = v - row * 20;
                const __nv_bfloat16* g = t ? g_B1 : g_B0;
                src = g + (size_t)(k0 + row) * NP + n0 + seg * 8;
                dst = stage + OFF_B0 + t * B_TILE + row * BROWB + seg * 16;
            } else {                        // A tiles: 2 x 256 units
                int u2  = u - 1280;
                int t   = u2 >= 256;
                int v   = u2 - t * 256;
                int row = v >> 2;
                int seg = v & 3;
                const __nv_bfloat16* g = t ? g_A1 : g_A0;
                src = g + (size_t)(m0 + row) * KP + k0 + seg * 8;
                dst = stage + OFF_A0 + t * A_TILE + row * AROWB + seg * 16;
            }
            CP_ASYNC16(dst, src);
        }
    }
}

// ---------------------------------------------------------------------------
// Split-bf16 HMMA GEMM: g_C = tanh(-(X @ WW)).
// CTA 64x160, 16 warps (16m x 40n each), BK=32 cp.async double-buffered.
// ---------------------------------------------------------------------------
__global__ __launch_bounds__(512, 1)
void gemm_mma_kernel() {
    extern __shared__ __align__(16) char smem[];
    const uint32_t sb = smem_u32(smem);
    const int tid  = threadIdx.x;
    const int lane = tid & 31;
    const int wid  = tid >> 5;
    const int wm   = wid & 3;        // 0..3 -> m offset wm*16
    const int wn   = wid >> 2;       // 0..3 -> n offset wn*40
    const int m0   = blockIdx.y * 64;
    const int n0   = blockIdx.x * 160;

    // ldmatrix lane addressing
    const int j = lane >> 3, rr = lane & 7;
    const uint32_t a_off  = (uint32_t)((wm * 16 + (j & 1) * 8 + rr) * AROWB + (j >> 1) * 16);
    const uint32_t b4_off = (uint32_t)(((j & 1) * 8 + rr) * BROWB + (j >> 1) * 16 + wn * 80);
    const uint32_t b2_off = (uint32_t)(((j & 1) * 8 + rr) * BROWB + wn * 80 + 64);

    float acc[5][4];
#pragma unroll
    for (int f = 0; f < 5; f++)
#pragma unroll
        for (int e = 0; e < 4; e++) acc[f][e] = 0.f;

    issue_chunk(sb, m0, n0, 0, tid);
    CP_COMMIT();

    for (int c = 0; c < NCHUNK; c++) {
        const uint32_t stage = sb + (uint32_t)(c & 1) * STAGE;
        if (c + 1 < NCHUNK) {
            issue_chunk(sb + (uint32_t)((c + 1) & 1) * STAGE, m0, n0,
                        (c + 1) * BK, tid);
            CP_COMMIT();
            CP_WAIT1();
        } else {
            CP_WAIT0();
        }
        __syncthreads();

#pragma unroll
        for (int ks = 0; ks < 2; ks++) {
            uint32_t A0f[4], A1f[4];
            LDSM4(A0f, stage + OFF_A0 + a_off + ks * 32);
            LDSM4(A1f, stage + OFF_A1 + a_off + ks * 32);
            uint32_t B0r[10], B1r[10];
#pragma unroll
            for (int f = 0; f < 2; f++) {
                LDSM4T(&B0r[4 * f], stage + OFF_B0 + b4_off + f * 32 + ks * 16 * BROWB);
                LDSM4T(&B1r[4 * f], stage + OFF_B1 + b4_off + f * 32 + ks * 16 * BROWB);
            }
            LDSM2T(&B0r[8], stage + OFF_B0 + b2_off + ks * 16 * BROWB);
            LDSM2T(&B1r[8], stage + OFF_B1 + b2_off + ks * 16 * BROWB);
#pragma unroll
            for (int f = 0; f < 5; f++) {
                MMA_BF16(acc[f], A0f, B0r[2 * f], B0r[2 * f + 1]);
                MMA_BF16(acc[f], A0f, B1r[2 * f], B1r[2 * f + 1]);
                MMA_BF16(acc[f], A1f, B0r[2 * f], B0r[2 * f + 1]);
            }
        }
        __syncthreads();
    }

    // Store with fused tanh(-x)
    const int gid = lane >> 2, tig = lane & 3;
    const int row = m0 + wm * 16 + gid;
    float* c0p = &g_C[(size_t)row * NN];
    float* c1p = &g_C[(size_t)(row + 8) * NN];
#pragma unroll
    for (int f = 0; f < 5; f++) {
        int col = n0 + wn * 40 + f * 8 + tig * 2;
        if (col < NN) {
            float2 lo, hi;
            lo.x = tanhf(-acc[f][0]);
            lo.y = tanhf(-acc[f][1]);
            hi.x = tanhf(-acc[f][2]);
            hi.y = tanhf(-acc[f][3]);
            *reinterpret_cast<float2*>(c0p + col) = lo;
            *reinterpret_cast<float2*>(c1p + col) = hi;
        }
    }
}

// ---------------------------------------------------------------------------
// Final combine (float4): out = lambd/belta * ( pf*OUT + 3*l*(A0NEW + c2*ANOLD) )
// ---------------------------------------------------------------------------
__global__ void epilogue_kernel(const float* __restrict__ lambd,
                                const float* __restrict__ l,
                                float* __restrict__ out) {
    int idx = blockIdx.x * blockDim.x + threadIdx.x;
    const int total4 = NB * NLAG * (NN / 4);     // 115200
    if (idx >= total4) return;
    int j4  = (idx % (NN / 4)) * 4;
    int lag = (idx / (NN / 4)) % NLAG;
    int b   = idx / ((NN / 4) * NLAG);
    int jm  = j4 % 200;

    int r = lag * NB + b;
    float4 o4 = *reinterpret_cast<const float4*>(&g_C[(size_t)r * NN + j4]);
    float4 a4 = *reinterpret_cast<const float4*>(&g_C[(size_t)(384 + r) * NN + j4]);
    float4 n4 = *reinterpret_cast<const float4*>(&g_C[(size_t)(768 + r) * NN + j4]);
    float4 lam = *reinterpret_cast<const float4*>(&lambd[lag * 200 + jm]);
    float4 lv  = *reinterpret_cast<const float4*>(&l[lag * 200 + jm]);

    float ib = 1.f / g_belta[lag];
    float pf = g_pf[lag];
    float c2 = g_c2[lag];

    float4 o;
    o.x = lam.x * ib * (pf * o4.x + 3.f * lv.x * (a4.x + c2 * n4.x));
    o.y = lam.y * ib * (pf * o4.y + 3.f * lv.y * (a4.y + c2 * n4.y));
    o.z = lam.z * ib * (pf * o4.z + 3.f * lv.z * (a4.z + c2 * n4.z));
    o.w = lam.w * ib * (pf * o4.w + 3.f * lv.w * (a4.w + c2 * n4.w));
    *reinterpret_cast<float4*>(&out[(size_t)idx * 4]) = o;
}

// ---------------------------------------------------------------------------
extern "C" void kernel_launch(void* const* d_in, const int* in_sizes, int n_in,
                              void* d_out, int out_size) {
    const float* A          = (const float*)d_in[0];
    const float* WW         = (const float*)d_in[1];
    const float* train_init = (const float*)d_in[2];
    const float* alpha      = (const float*)d_in[3];
    const float* fract      = (const float*)d_in[4];
    const float* lambd      = (const float*)d_in[5];
    const float* l          = (const float*)d_in[6];
    float* out = (float*)d_out;

    cudaFuncSetAttribute(gemm_mma_kernel,
                         cudaFuncAttributeMaxDynamicSharedMemorySize,
                         2 * STAGE);

    scalars_kernel<<<1, 32>>>(alpha, fract);

    pack_A_kernel<<<(MROWS * KP + 255) / 256, 256>>>(A, train_init);
    pack_B_kernel<<<(KP * (NP / 2) + 255) / 256, 256>>>(WW);

    dim3 ggrid(NP / 160, MROWS / 64);             // (8, 18) = 144 CTAs
    gemm_mma_kernel<<<ggrid, 512, 2 * STAGE>>>();

    const int total4 = NB * NLAG * (NN / 4);
    epilogue_kernel<<<(total4 + 255) / 256, 256>>>(lambd, l, out);
}

// round 6
// speedup vs baseline: 5.1847x; 1.3083x over previous
#include <cuda_runtime.h>
#include <cuda_bf16.h>
#include <math_constants.h>
#include <cstdint>

// Problem constants
#define NLAG   12
#define NB     32
#define NN     1200
#define MROWS  1152          // 3 * NLAG * NB
#define KDIM   1200
#define KP     1216          // K padded to 38*32
#define NP     1280          // B storage width (padded)

// GEMM tiling: CTA 64m x 80n, BK=32, 256 threads (8 warps = 4m x 2n, 16x40 each)
#define BK      32
#define NCHUNK  (KP / BK)    // 38
#define AROWB   80           // A smem row pitch
#define BROWB   176          // B smem row pitch (80 bf16 = 160B + 16B pad)
#define A_TILE  (64 * AROWB)     // 5120
#define B_TILE  (32 * BROWB)     // 5632
#define OFF_A0  0
#define OFF_A1  A_TILE
#define OFF_B0  (2 * A_TILE)
#define OFF_B1  (2 * A_TILE + B_TILE)
#define STAGE   (2 * A_TILE + 2 * B_TILE)   // 21504
#define NUNITS  1152         // 16B units per chunk: B 2*320 + A 2*256

// Scratch (device globals; no allocation allowed)
__device__ __align__(16) __nv_bfloat16 g_A0[MROWS * KP];
__device__ __align__(16) __nv_bfloat16 g_A1[MROWS * KP];
__device__ __align__(16) __nv_bfloat16 g_B0[KP * NP];    // k-major
__device__ __align__(16) __nv_bfloat16 g_B1[KP * NP];
__device__ __align__(16) float g_C[MROWS * NN];
__device__ float g_belta[NLAG];
__device__ float g_c2[NLAG];
__device__ float g_pf[NLAG];

// ---------------------------------------------------------------------------
__device__ __forceinline__ uint32_t smem_u32(const void* p) {
    uint32_t a;
    asm("{ .reg .u64 t; cvta.to.shared.u64 t, %1; cvt.u32.u64 %0, t; }"
        : "=r"(a) : "l"(p));
    return a;
}

#define LDSM4(r, addr)                                                      \
    asm volatile("ldmatrix.sync.aligned.m8n8.x4.shared.b16 "                \
                 "{%0, %1, %2, %3}, [%4];"                                  \
                 : "=r"((r)[0]), "=r"((r)[1]), "=r"((r)[2]), "=r"((r)[3])   \
                 : "r"(addr))
#define LDSM4T(r, addr)                                                     \
    asm volatile("ldmatrix.sync.aligned.m8n8.x4.trans.shared.b16 "          \
                 "{%0, %1, %2, %3}, [%4];"                                  \
                 : "=r"((r)[0]), "=r"((r)[1]), "=r"((r)[2]), "=r"((r)[3])   \
                 : "r"(addr))
#define LDSM2T(r, addr)                                                     \
    asm volatile("ldmatrix.sync.aligned.m8n8.x2.trans.shared.b16 "          \
                 "{%0, %1}, [%2];"                                          \
                 : "=r"((r)[0]), "=r"((r)[1]) : "r"(addr))

#define MMA_BF16(c, a, bb0, bb1)                                            \
    asm volatile("mma.sync.aligned.m16n8k16.row.col.f32.bf16.bf16.f32 "     \
                 "{%0, %1, %2, %3}, {%4, %5, %6, %7}, {%8, %9}, "           \
                 "{%0, %1, %2, %3};"                                        \
                 : "+f"((c)[0]), "+f"((c)[1]), "+f"((c)[2]), "+f"((c)[3])   \
                 : "r"((a)[0]), "r"((a)[1]), "r"((a)[2]), "r"((a)[3]),      \
                   "r"(bb0), "r"(bb1))

#define CP_ASYNC16(dst, src)                                                \
    asm volatile("cp.async.cg.shared.global [%0], [%1], 16;"                \
                 :: "r"(dst), "l"(__cvta_generic_to_global(src)))
#define CP_COMMIT() asm volatile("cp.async.commit_group;" ::: "memory")
#define CP_WAIT1()  asm volatile("cp.async.wait_group 1;" ::: "memory")
#define CP_WAIT0()  asm volatile("cp.async.wait_group 0;" ::: "memory")

// ---------------------------------------------------------------------------
__device__ __forceinline__ float gamma_fn(float x) {
    if (x > 0.f) return expf(lgammaf(x));
    return CUDART_PI_F / (sinf(CUDART_PI_F * x) * expf(lgammaf(1.f - x)));
}

// ---------------------------------------------------------------------------
// Fused prep: per-lag scalars + pack A (3 stacked slices, split bf16)
//           + pack B (k-major split bf16).
// Index space: [0, MROWS*KP) -> A, [MROWS*KP, MROWS*KP + KP*NP/2) -> B pairs.
// ---------------------------------------------------------------------------
#define A_ELEMS (MROWS * KP)
#define B_PAIRS (KP * (NP / 2))

__global__ void prep_kernel(const float* __restrict__ A,
                            const float* __restrict__ WW,
                            const float* __restrict__ train_init,
                            const float* __restrict__ alpha,
                            const float* __restrict__ fract) {
    int idx = blockIdx.x * blockDim.x + threadIdx.x;

    if (blockIdx.x == 0 && threadIdx.x < NLAG) {
        int lag = threadIdx.x;
        float a   = alpha[lag];
        float f   = fract[lag];
        float ga1 = gamma_fn(a + 1.f);
        float gm2 = gamma_fn(a - 2.f);
        float belta = 1.f
                    + ga1 / gamma_fn(a)
                    + ga1 / (2.f * gamma_fn(a - 1.f))
                    + ga1 / (6.f * gm2);
        g_belta[lag] = belta;
        g_c2[lag]    = ga1 / (6.f * gm2);
        g_pf[lag]    = 2.f * powf(3.f, f);
    }

    if (idx < A_ELEMS) {
        int r = idx / KP;
        int k = idx - r * KP;
        float v = 0.f;
        if (k < KDIM) {
            if (r < 384) {
                v = A[r * KDIM + k];
            } else {
                int rr  = r - 384;
                int mat = rr / 384;
                rr      = rr % 384;
                int lag = rr / NB;
                int b   = rr % NB;
                int lagidx = (mat == 0) ? (lag + 1) : lag;
                v = train_init[((b * NN + k) * 13 + lagidx) * 2 + 1];
            }
        }
        __nv_bfloat16 hi = __float2bfloat16(v);
        __nv_bfloat16 lo = __float2bfloat16(v - __bfloat162float(hi));
        g_A0[idx] = hi;
        g_A1[idx] = lo;
    } else if (idx < A_ELEMS + B_PAIRS) {
        int p = idx - A_ELEMS;
        int k = p / (NP / 2);
        int n = (p - k * (NP / 2)) * 2;
        float v0 = 0.f, v1 = 0.f;
        if (k < KDIM && n + 1 < NN) {
            float2 w = *reinterpret_cast<const float2*>(&WW[k * NN + n]);
            v0 = w.x; v1 = w.y;
        } else if (k < KDIM && n < NN) {
            v0 = WW[k * NN + n];
        }
        __nv_bfloat16 h0 = __float2bfloat16(v0);
        __nv_bfloat16 l0 = __float2bfloat16(v0 - __bfloat162float(h0));
        __nv_bfloat16 h1 = __float2bfloat16(v1);
        __nv_bfloat16 l1 = __float2bfloat16(v1 - __bfloat162float(h1));
        reinterpret_cast<__nv_bfloat162*>(g_B0)[p] = __halves2bfloat162(h0, h1);
        reinterpret_cast<__nv_bfloat162*>(g_B1)[p] = __halves2bfloat162(l0, l1);
    }
}

// ---------------------------------------------------------------------------
// cp.async issue for one chunk: 1152 16B units (B0,B1: 32x160B; A0,A1: 64x64B)
// ---------------------------------------------------------------------------
__device__ __forceinline__ void issue_chunk(uint32_t stage, int m0, int n0,
                                            int k0, int tid) {
#pragma unroll
    for (int i = 0; i < 5; i++) {
        int u = tid + i * 256;
        if (u < NUNITS) {
            uint32_t dst;
            const __nv_bfloat16* src;
            if (u < 640) {                  // B tiles: 2 x 320 units
                int t   = u >= 320;
                int v   = u - t * 320;
                int row = v / 10;
                int seg = v - row * 10;
                const __nv_bfloat16* g = t ? g_B1 : g_B0;
                src = g + (size_t)(k0 + row) * NP + n0 + seg * 8;
                dst = stage + OFF_B0 + t * B_TILE + row * BROWB + seg * 16;
            } else {                        // A tiles: 2 x 256 units
                int u2  = u - 640;
                int t   = u2 >= 256;
                int v   = u2 - t * 256;
                int row = v >> 2;
                int seg = v & 3;
                const __nv_bfloat16* g = t ? g_A1 : g_A0;
                src = g + (size_t)(m0 + row) * KP + k0 + seg * 8;
                dst = stage + OFF_A0 + t * A_TILE + row * AROWB + seg * 16;
            }
            CP_ASYNC16(dst, src);
        }
    }
}

// ---------------------------------------------------------------------------
// Split-bf16 HMMA GEMM: g_C = tanh(-(X @ WW)).
// CTA 64x80, 8 warps (16m x 40n each), BK=32 cp.async double-buffered.
// Grid (15, 18): 15*80 = 1200 = NN exactly (no wasted columns).
// ---------------------------------------------------------------------------
__global__ __launch_bounds__(256, 3)
void gemm_mma_kernel() {
    extern __shared__ __align__(16) char smem[];
    const uint32_t sb = smem_u32(smem);
    const int tid  = threadIdx.x;
    const int lane = tid & 31;
    const int wid  = tid >> 5;
    const int wm   = wid & 3;        // 0..3 -> m offset wm*16
    const int wn   = wid >> 2;       // 0..1 -> n offset wn*40
    const int m0   = blockIdx.y * 64;
    const int n0   = blockIdx.x * 80;

    // ldmatrix lane addressing
    const int j = lane >> 3, rr = lane & 7;
    const uint32_t a_off  = (uint32_t)((wm * 16 + (j & 1) * 8 + rr) * AROWB + (j >> 1) * 16);
    const uint32_t b4_off = (uint32_t)(((j & 1) * 8 + rr) * BROWB + (j >> 1) * 16 + wn * 80);
    const uint32_t b2_off = (uint32_t)(((j & 1) * 8 + rr) * BROWB + wn * 80 + 64);

    float acc[5][4];
#pragma unroll
    for (int f = 0; f < 5; f++)
#pragma unroll
        for (int e = 0; e < 4; e++) acc[f][e] = 0.f;

    issue_chunk(sb, m0, n0, 0, tid);
    CP_COMMIT();

    for (int c = 0; c < NCHUNK; c++) {
        const uint32_t stage = sb + (uint32_t)(c & 1) * STAGE;
        if (c + 1 < NCHUNK) {
            issue_chunk(sb + (uint32_t)((c + 1) & 1) * STAGE, m0, n0,
                        (c + 1) * BK, tid);
            CP_COMMIT();
            CP_WAIT1();
        } else {
            CP_WAIT0();
        }
        __syncthreads();

#pragma unroll
        for (int ks = 0; ks < 2; ks++) {
            uint32_t A0f[4], A1f[4];
            LDSM4(A0f, stage + OFF_A0 + a_off + ks * 32);
            LDSM4(A1f, stage + OFF_A1 + a_off + ks * 32);
            uint32_t B0r[10], B1r[10];
#pragma unroll
            for (int f = 0; f < 2; f++) {
                LDSM4T(&B0r[4 * f], stage + OFF_B0 + b4_off + f * 32 + ks * 16 * BROWB);
                LDSM4T(&B1r[4 * f], stage + OFF_B1 + b4_off + f * 32 + ks * 16 * BROWB);
            }
            LDSM2T(&B0r[8], stage + OFF_B0 + b2_off + ks * 16 * BROWB);
            LDSM2T(&B1r[8], stage + OFF_B1 + b2_off + ks * 16 * BROWB);
#pragma unroll
            for (int f = 0; f < 5; f++) {
                MMA_BF16(acc[f], A0f, B0r[2 * f], B0r[2 * f + 1]);
                MMA_BF16(acc[f], A0f, B1r[2 * f], B1r[2 * f + 1]);
                MMA_BF16(acc[f], A1f, B0r[2 * f], B0r[2 * f + 1]);
            }
        }
        __syncthreads();
    }

    // Store with fused tanh(-x); cols always < 1200 (grid.x*80 == NN).
    const int gid = lane >> 2, tig = lane & 3;
    const int row = m0 + wm * 16 + gid;
    float* c0p = &g_C[(size_t)row * NN];
    float* c1p = &g_C[(size_t)(row + 8) * NN];
#pragma unroll
    for (int f = 0; f < 5; f++) {
        int col = n0 + wn * 40 + f * 8 + tig * 2;
        float2 lo, hi;
        lo.x = tanhf(-acc[f][0]);
        lo.y = tanhf(-acc[f][1]);
        hi.x = tanhf(-acc[f][2]);
        hi.y = tanhf(-acc[f][3]);
        *reinterpret_cast<float2*>(c0p + col) = lo;
        *reinterpret_cast<float2*>(c1p + col) = hi;
    }
}

// ---------------------------------------------------------------------------
// Final combine (float4): out = lambd/belta * ( pf*OUT + 3*l*(A0NEW + c2*ANOLD) )
// ---------------------------------------------------------------------------
__global__ void epilogue_kernel(const float* __restrict__ lambd,
                                const float* __restrict__ l,
                                float* __restrict__ out) {
    int idx = blockIdx.x * blockDim.x + threadIdx.x;
    const int total4 = NB * NLAG * (NN / 4);     // 115200
    if (idx >= total4) return;
    int j4  = (idx % (NN / 4)) * 4;
    int lag = (idx / (NN / 4)) % NLAG;
    int b   = idx / ((NN / 4) * NLAG);
    int jm  = j4 % 200;

    int r = lag * NB + b;
    float4 o4 = *reinterpret_cast<const float4*>(&g_C[(size_t)r * NN + j4]);
    float4 a4 = *reinterpret_cast<const float4*>(&g_C[(size_t)(384 + r) * NN + j4]);
    float4 n4 = *reinterpret_cast<const float4*>(&g_C[(size_t)(768 + r) * NN + j4]);
    float4 lam = *reinterpret_cast<const float4*>(&lambd[lag * 200 + jm]);
    float4 lv  = *reinterpret_cast<const float4*>(&l[lag * 200 + jm]);

    float ib = 1.f / g_belta[lag];
    float pf = g_pf[lag];
    float c2 = g_c2[lag];

    float4 o;
    o.x = lam.x * ib * (pf * o4.x + 3.f * lv.x * (a4.x + c2 * n4.x));
    o.y = lam.y * ib * (pf * o4.y + 3.f * lv.y * (a4.y + c2 * n4.y));
    o.z = lam.z * ib * (pf * o4.z + 3.f * lv.z * (a4.z + c2 * n4.z));
    o.w = lam.w * ib * (pf * o4.w + 3.f * lv.w * (a4.w + c2 * n4.w));
    *reinterpret_cast<float4*>(&out[(size_t)idx * 4]) = o;
}

// ---------------------------------------------------------------------------
extern "C" void kernel_launch(void* const* d_in, const int* in_sizes, int n_in,
                              void* d_out, int out_size) {
    const float* A          = (const float*)d_in[0];
    const float* WW         = (const float*)d_in[1];
    const float* train_init = (const float*)d_in[2];
    const float* alpha      = (const float*)d_in[3];
    const float* fract      = (const float*)d_in[4];
    const float* lambd      = (const float*)d_in[5];
    const float* l          = (const float*)d_in[6];
    float* out = (float*)d_out;

    cudaFuncSetAttribute(gemm_mma_kernel,
                         cudaFuncAttributeMaxDynamicSharedMemorySize,
                         2 * STAGE);

    const int prepN = A_ELEMS + B_PAIRS;
    prep_kernel<<<(prepN + 255) / 256, 256>>>(A, WW, train_init, alpha, fract);

    dim3 ggrid(NN / 80, MROWS / 64);              // (15, 18) = 270 CTAs
    gemm_mma_kernel<<<ggrid, 256, 2 * STAGE>>>();

    const int total4 = NB * NLAG * (NN / 4);
    epilogue_kernel<<<(total4 + 255) / 256, 256>>>(lambd, l, out);
}